// round 2
// baseline (speedup 1.0000x reference)
#include <cuda_runtime.h>
#include <math.h>

#define NNODE 100000
#define NF 128
#define NCLS 40

// Scratch ping-pong buffers (allocation-free rule: __device__ globals)
__device__ float g_bufA[(size_t)NNODE * NF];
__device__ float g_bufB[(size_t)NNODE * NF];

// ---------------------------------------------------------------------------
// zero fill
// ---------------------------------------------------------------------------
__global__ void zero_kernel(float4* __restrict__ p, int n4) {
    int i = blockIdx.x * blockDim.x + threadIdx.x;
    if (i < n4) p[i] = make_float4(0.f, 0.f, 0.f, 0.f);
}

// ---------------------------------------------------------------------------
// SpMM: Y[dst] += vals * (optionally M[src] *) X[src]
// one warp per edge; lane handles 4 consecutive features; vectorized REDG
// ---------------------------------------------------------------------------
template <bool USE_M>
__global__ __launch_bounds__(256) void spmm_kernel(
    const float* __restrict__ X, const float* __restrict__ Mv,
    const int* __restrict__ src, const int* __restrict__ dst,
    const float* __restrict__ vals, float* __restrict__ Y, int E)
{
    int w = (blockIdx.x * 256 + (int)threadIdx.x) >> 5;
    if (w >= E) return;
    int lane = threadIdx.x & 31;
    int s = src[w];
    int d = dst[w];
    float v = vals[w];
    if (USE_M) v *= Mv[s];
    const float4 xv = *(const float4*)(X + (size_t)s * NF + lane * 4);
    float rx = v * xv.x, ry = v * xv.y, rz = v * xv.z, rw = v * xv.w;
    float* addr = Y + (size_t)d * NF + lane * 4;
    asm volatile("red.global.add.v4.f32 [%0], {%1, %2, %3, %4};"
                 :: "l"(addr), "f"(rx), "f"(ry), "f"(rz), "f"(rw)
                 : "memory");
}

// ---------------------------------------------------------------------------
// GEMM + bias + BN(eval) + ReLU:  Y[n,o] = relu(bn(am[n]*sum_k X[n,k]*W[o,k] + b[o]))
// BM=64 rows, BN=128 cols (full), BK=32. 256 threads, 8x4 micro-tile.
// Xs stored k-major so the a-fragment is a float4 broadcast load.
// ---------------------------------------------------------------------------
#define GBM 64
#define GBK 32

__global__ __launch_bounds__(256) void gemm_bn_relu_kernel(
    const float* __restrict__ X, const float* __restrict__ W,
    const float* __restrict__ bias, const float* __restrict__ gamma,
    const float* __restrict__ beta, const float* __restrict__ rmean,
    const float* __restrict__ rvar, const float* __restrict__ am,
    float* __restrict__ Y, int n)
{
    __shared__ float Xs[GBK][GBM];    // [k][m]  8KB
    __shared__ float Ws[GBK][NF];     // [k][o] 16KB

    int m0  = blockIdx.x * GBM;
    int tid = threadIdx.x;
    int ty  = tid >> 5;    // 0..7 (row group of 8)
    int tx  = tid & 31;    // 0..31 (col group of 4)

    float acc[8][4];
    #pragma unroll
    for (int i = 0; i < 8; i++)
        #pragma unroll
        for (int j = 0; j < 4; j++) acc[i][j] = 0.f;

    for (int k0 = 0; k0 < NF; k0 += GBK) {
        // load X tile 64x32 (512 float4s, 2 per thread), transpose into Xs[k][m]
        #pragma unroll
        for (int q = 0; q < 2; q++) {
            int idx = tid * 2 + q;          // 0..511
            int r   = idx >> 3;             // 0..63
            int kc  = (idx & 7) * 4;        // 0,4,..28
            float4 v = make_float4(0.f, 0.f, 0.f, 0.f);
            int gr = m0 + r;
            if (gr < n) v = *(const float4*)(X + (size_t)gr * NF + k0 + kc);
            Xs[kc + 0][r] = v.x;
            Xs[kc + 1][r] = v.y;
            Xs[kc + 2][r] = v.z;
            Xs[kc + 3][r] = v.w;
        }
        // load W tile 128x32 (1024 float4s, 4 per thread), transpose into Ws[k][o]
        #pragma unroll
        for (int q = 0; q < 4; q++) {
            int idx = tid * 4 + q;          // 0..1023
            int o   = idx >> 3;             // 0..127
            int kc  = (idx & 7) * 4;
            float4 v = *(const float4*)(W + (size_t)o * NF + k0 + kc);
            Ws[kc + 0][o] = v.x;
            Ws[kc + 1][o] = v.y;
            Ws[kc + 2][o] = v.z;
            Ws[kc + 3][o] = v.w;
        }
        __syncthreads();

        #pragma unroll
        for (int k = 0; k < GBK; k++) {
            float4 b  = *(const float4*)&Ws[k][tx * 4];
            float4 a0 = *(const float4*)&Xs[k][ty * 8];
            float4 a1 = *(const float4*)&Xs[k][ty * 8 + 4];
            float a[8] = {a0.x, a0.y, a0.z, a0.w, a1.x, a1.y, a1.z, a1.w};
            #pragma unroll
            for (int i = 0; i < 8; i++) {
                acc[i][0] += a[i] * b.x;
                acc[i][1] += a[i] * b.y;
                acc[i][2] += a[i] * b.z;
                acc[i][3] += a[i] * b.w;
            }
        }
        __syncthreads();
    }

    // epilogue: per-column BN constants
    int c0 = tx * 4;
    float bs[4], sc[4], sh[4];
    #pragma unroll
    for (int j = 0; j < 4; j++) {
        int c = c0 + j;
        float s = gamma[c] * rsqrtf(rvar[c] + 1e-5f);
        sc[j] = s;
        sh[j] = beta[c] - rmean[c] * s;
        bs[j] = bias[c];
    }
    #pragma unroll
    for (int i = 0; i < 8; i++) {
        int r = m0 + ty * 8 + i;
        if (r < n) {
            float a = (am != nullptr) ? am[r] : 1.0f;
            float4 o;
            o.x = fmaxf((acc[i][0] * a + bs[0]) * sc[0] + sh[0], 0.f);
            o.y = fmaxf((acc[i][1] * a + bs[1]) * sc[1] + sh[1], 0.f);
            o.z = fmaxf((acc[i][2] * a + bs[2]) * sc[2] + sh[2], 0.f);
            o.w = fmaxf((acc[i][3] * a + bs[3]) * sc[3] + sh[3], 0.f);
            *(float4*)(Y + (size_t)r * NF + c0) = o;
        }
    }
}

// ---------------------------------------------------------------------------
// Final layer: out[n,c] = log_softmax(sum_k X[n,k]*W2[c,k] + b2[c])
// warp-per-node, W2 (40x128) in smem, butterfly reductions.
// ---------------------------------------------------------------------------
__global__ __launch_bounds__(128) void gemm2_lsm_kernel(
    const float* __restrict__ X, const float* __restrict__ W2,
    const float* __restrict__ b2, float* __restrict__ out, int n)
{
    __shared__ float Wsm[NCLS * NF];
    __shared__ float bsm[NCLS];
    for (int i = threadIdx.x; i < NCLS * NF / 4; i += 128)
        ((float4*)Wsm)[i] = ((const float4*)W2)[i];
    if (threadIdx.x < NCLS) bsm[threadIdx.x] = b2[threadIdx.x];
    __syncthreads();

    int lane = threadIdx.x & 31;
    int warp = threadIdx.x >> 5;

    for (int node = blockIdx.x * 4 + warp; node < n; node += gridDim.x * 4) {
        float4 xv = *(const float4*)(X + (size_t)node * NF + lane * 4);
        float v0 = 0.f, v1 = -INFINITY;
        #pragma unroll
        for (int c = 0; c < NCLS; c++) {
            float4 wv = *(const float4*)&Wsm[c * NF + lane * 4];
            float p = xv.x * wv.x + xv.y * wv.y + xv.z * wv.z + xv.w * wv.w;
            p += __shfl_xor_sync(0xffffffffu, p, 16);
            p += __shfl_xor_sync(0xffffffffu, p, 8);
            p += __shfl_xor_sync(0xffffffffu, p, 4);
            p += __shfl_xor_sync(0xffffffffu, p, 2);
            p += __shfl_xor_sync(0xffffffffu, p, 1);
            p += bsm[c];
            if (c == lane) v0 = p;
            if (c == lane + 32) v1 = p;
        }
        // stable log_softmax over 40 values (lanes 0..31 hold c<32; lanes 0..7 hold c+32)
        float mx = v0;
        if (lane < 8) mx = fmaxf(mx, v1);
        #pragma unroll
        for (int m = 16; m; m >>= 1) mx = fmaxf(mx, __shfl_xor_sync(0xffffffffu, mx, m));
        float e = __expf(v0 - mx) + ((lane < 8) ? __expf(v1 - mx) : 0.f);
        #pragma unroll
        for (int m = 16; m; m >>= 1) e += __shfl_xor_sync(0xffffffffu, e, m);
        float lse = logf(e) + mx;
        out[(size_t)node * NCLS + lane] = v0 - lse;
        if (lane < 8) out[(size_t)node * NCLS + 32 + lane] = v1 - lse;
    }
}

// ---------------------------------------------------------------------------
// launch
// ---------------------------------------------------------------------------
extern "C" void kernel_launch(void* const* d_in, const int* in_sizes, int n_in,
                              void* d_out, int out_size)
{
    const float* x     = (const float*)d_in[0];
    const float* M     = (const float*)d_in[1];
    const float* AM    = (const float*)d_in[2];
    const int*   srcZ  = (const int*)  d_in[3];
    const int*   dstZ  = (const int*)  d_in[4];
    const float* valsZ = (const float*)d_in[5];
    const int*   src   = (const int*)  d_in[6];
    const int*   dst   = (const int*)  d_in[7];
    const float* vals  = (const float*)d_in[8];
    const float* W0  = (const float*)d_in[9];
    const float* b0  = (const float*)d_in[10];
    const float* g0  = (const float*)d_in[11];
    const float* be0 = (const float*)d_in[12];
    const float* rm0 = (const float*)d_in[13];
    const float* rv0 = (const float*)d_in[14];
    const float* W1  = (const float*)d_in[15];
    const float* b1  = (const float*)d_in[16];
    const float* g1  = (const float*)d_in[17];
    const float* be1 = (const float*)d_in[18];
    const float* rm1 = (const float*)d_in[19];
    const float* rv1 = (const float*)d_in[20];
    const float* W2  = (const float*)d_in[21];
    const float* b2  = (const float*)d_in[22];
    float* out = (float*)d_out;

    int n = in_sizes[1];  // M has N elements
    int E = in_sizes[3];  // srcZ has E elements

    float *bufA, *bufB;
    cudaGetSymbolAddress((void**)&bufA, g_bufA);
    cudaGetSymbolAddress((void**)&bufB, g_bufB);

    int n4    = n * (NF / 4);
    int zgrid = (n4 + 255) / 256;
    int egrid = (E + 7) / 8;       // one warp per edge, 8 warps per block
    int ggrid = (n + GBM - 1) / GBM;

    // layer 0: h = bn_relu((spmm(adjZ, M*x) * AM) @ W0^T + b0)
    zero_kernel<<<zgrid, 256>>>((float4*)bufA, n4);
    spmm_kernel<true><<<egrid, 256>>>(x, M, srcZ, dstZ, valsZ, bufA, E);
    gemm_bn_relu_kernel<<<ggrid, 256>>>(bufA, W0, b0, g0, be0, rm0, rv0, AM, bufB, n);

    // layer 1: h = bn_relu(spmm(adj, h) @ W1^T + b1)
    zero_kernel<<<zgrid, 256>>>((float4*)bufA, n4);
    spmm_kernel<false><<<egrid, 256>>>(bufB, nullptr, src, dst, vals, bufA, E);
    gemm_bn_relu_kernel<<<ggrid, 256>>>(bufA, W1, b1, g1, be1, rm1, rv1, nullptr, bufB, n);

    // layer 2: out = log_softmax(spmm(adj, h) @ W2^T + b2)
    zero_kernel<<<zgrid, 256>>>((float4*)bufA, n4);
    spmm_kernel<false><<<egrid, 256>>>(bufB, nullptr, src, dst, vals, bufA, E);
    gemm2_lsm_kernel<<<2048, 128>>>(bufA, W2, b2, out, n);
}

// round 3
// speedup vs baseline: 1.3494x; 1.3494x over previous
#include <cuda_runtime.h>
#include <math.h>

#define NNODE 100000
#define NF 128
#define NCLS 40
#define EMAX 1600000

// ---------------------------------------------------------------------------
// Static device scratch (allocation-free rule)
// ---------------------------------------------------------------------------
__device__ float g_bufA[(size_t)NNODE * NF];
__device__ float g_bufB[(size_t)NNODE * NF];
__device__ float g_t40[(size_t)NNODE * NCLS];
__device__ float g_o40[(size_t)NNODE * NCLS];
__device__ int   g_rpZ[NNODE + 1];
__device__ int   g_rpA[NNODE + 1];
__device__ int   g_cnt[NNODE];
__device__ int   g_cur[NNODE];
__device__ int   g_srcZp[EMAX];
__device__ float g_valZp[EMAX];
__device__ int   g_srcAp[EMAX];
__device__ float g_valAp[EMAX];

// ---------------------------------------------------------------------------
// CSR build: count -> scan -> fill (permute src/vals into CSR order)
// ---------------------------------------------------------------------------
__global__ void zero2_int_kernel(int* __restrict__ a, int* __restrict__ b, int n) {
    int i = blockIdx.x * blockDim.x + threadIdx.x;
    if (i < n) { a[i] = 0; b[i] = 0; }
}

__global__ void count_kernel(const int* __restrict__ dst, int* __restrict__ cnt, int E) {
    int e = blockIdx.x * blockDim.x + threadIdx.x;
    if (e < E) atomicAdd(&cnt[dst[e]], 1);
}

// Single-block exclusive scan of cnt[0..n) into rp, rp[n] = total.
__global__ __launch_bounds__(1024) void scan_kernel(const int* __restrict__ cnt,
                                                    int* __restrict__ rp, int n) {
    __shared__ int sums[1024];
    int t = threadIdx.x;
    int chunk = (n + 1023) >> 10;
    int lo = t * chunk;
    int hi = min(lo + chunk, n);
    int s = 0;
    for (int i = lo; i < hi; i++) s += cnt[i];
    sums[t] = s;
    __syncthreads();
    for (int d = 1; d < 1024; d <<= 1) {
        int v = (t >= d) ? sums[t - d] : 0;
        __syncthreads();
        sums[t] += v;
        __syncthreads();
    }
    int off = t ? sums[t - 1] : 0;
    for (int i = lo; i < hi; i++) { rp[i] = off; off += cnt[i]; }
    if (t == 1023) rp[n] = sums[1023];
}

// Permute src/vals into CSR order. For the adjZ graph, fold M[src] into the value.
__global__ void fill_kernel(const int* __restrict__ src, const int* __restrict__ dst,
                            const float* __restrict__ vals, const float* __restrict__ Mv,
                            const int* __restrict__ rp, int* __restrict__ cur,
                            int* __restrict__ srcp, float* __restrict__ valp, int E) {
    int e = blockIdx.x * blockDim.x + threadIdx.x;
    if (e >= E) return;
    int d = dst[e];
    int slot = rp[d] + atomicAdd(&cur[d], 1);
    int s = src[e];
    float v = vals[e];
    if (Mv != nullptr) v *= Mv[s];
    srcp[slot] = s;
    valp[slot] = v;
}

// ---------------------------------------------------------------------------
// Gather SpMM (128-wide): one warp per destination node, acc in registers.
// ---------------------------------------------------------------------------
__global__ __launch_bounds__(256) void spmm_gather128(
    const float* __restrict__ X, const int* __restrict__ srcp,
    const float* __restrict__ valp, const int* __restrict__ rp,
    float* __restrict__ Y, int n)
{
    int w = (blockIdx.x * 256 + (int)threadIdx.x) >> 5;
    if (w >= n) return;
    int lane = threadIdx.x & 31;
    int beg = rp[w], end = rp[w + 1];
    float4 acc = make_float4(0.f, 0.f, 0.f, 0.f);
    #pragma unroll 4
    for (int j = beg; j < end; j++) {
        int   s = srcp[j];
        float v = valp[j];
        float4 xv = *(const float4*)(X + (size_t)s * NF + lane * 4);
        acc.x += v * xv.x; acc.y += v * xv.y;
        acc.z += v * xv.z; acc.w += v * xv.w;
    }
    *(float4*)(Y + (size_t)w * NF + lane * 4) = acc;
}

// ---------------------------------------------------------------------------
// Gather SpMM (40-wide): 10-lane group per node, 3 nodes per warp.
// ---------------------------------------------------------------------------
__global__ __launch_bounds__(256) void spmm_gather40(
    const float* __restrict__ T, const int* __restrict__ srcp,
    const float* __restrict__ valp, const int* __restrict__ rp,
    float* __restrict__ O, int n)
{
    int gw = (blockIdx.x * 256 + (int)threadIdx.x) >> 5;
    int lane = threadIdx.x & 31;
    int grp = lane / 10;
    int l   = lane - grp * 10;
    if (grp >= 3) return;
    int node = gw * 3 + grp;
    if (node >= n) return;
    int beg = rp[node], end = rp[node + 1];
    float4 acc = make_float4(0.f, 0.f, 0.f, 0.f);
    #pragma unroll 4
    for (int j = beg; j < end; j++) {
        int   s = srcp[j];
        float v = valp[j];
        float4 tv = *(const float4*)(T + (size_t)s * NCLS + l * 4);
        acc.x += v * tv.x; acc.y += v * tv.y;
        acc.z += v * tv.z; acc.w += v * tv.w;
    }
    *(float4*)(O + (size_t)node * NCLS + l * 4) = acc;
}

// ---------------------------------------------------------------------------
// GEMM + bias + BN(eval) + ReLU (unchanged from R2, measured-good)
// ---------------------------------------------------------------------------
#define GBM 64
#define GBK 32

__global__ __launch_bounds__(256) void gemm_bn_relu_kernel(
    const float* __restrict__ X, const float* __restrict__ W,
    const float* __restrict__ bias, const float* __restrict__ gamma,
    const float* __restrict__ beta, const float* __restrict__ rmean,
    const float* __restrict__ rvar, const float* __restrict__ am,
    float* __restrict__ Y, int n)
{
    __shared__ float Xs[GBK][GBM];
    __shared__ float Ws[GBK][NF];

    int m0  = blockIdx.x * GBM;
    int tid = threadIdx.x;
    int ty  = tid >> 5;
    int tx  = tid & 31;

    float acc[8][4];
    #pragma unroll
    for (int i = 0; i < 8; i++)
        #pragma unroll
        for (int j = 0; j < 4; j++) acc[i][j] = 0.f;

    for (int k0 = 0; k0 < NF; k0 += GBK) {
        #pragma unroll
        for (int q = 0; q < 2; q++) {
            int idx = tid * 2 + q;
            int r   = idx >> 3;
            int kc  = (idx & 7) * 4;
            float4 v = make_float4(0.f, 0.f, 0.f, 0.f);
            int gr = m0 + r;
            if (gr < n) v = *(const float4*)(X + (size_t)gr * NF + k0 + kc);
            Xs[kc + 0][r] = v.x;
            Xs[kc + 1][r] = v.y;
            Xs[kc + 2][r] = v.z;
            Xs[kc + 3][r] = v.w;
        }
        #pragma unroll
        for (int q = 0; q < 4; q++) {
            int idx = tid * 4 + q;
            int o   = idx >> 3;
            int kc  = (idx & 7) * 4;
            float4 v = *(const float4*)(W + (size_t)o * NF + k0 + kc);
            Ws[kc + 0][o] = v.x;
            Ws[kc + 1][o] = v.y;
            Ws[kc + 2][o] = v.z;
            Ws[kc + 3][o] = v.w;
        }
        __syncthreads();

        #pragma unroll
        for (int k = 0; k < GBK; k++) {
            float4 b  = *(const float4*)&Ws[k][tx * 4];
            float4 a0 = *(const float4*)&Xs[k][ty * 8];
            float4 a1 = *(const float4*)&Xs[k][ty * 8 + 4];
            float a[8] = {a0.x, a0.y, a0.z, a0.w, a1.x, a1.y, a1.z, a1.w};
            #pragma unroll
            for (int i = 0; i < 8; i++) {
                acc[i][0] += a[i] * b.x;
                acc[i][1] += a[i] * b.y;
                acc[i][2] += a[i] * b.z;
                acc[i][3] += a[i] * b.w;
            }
        }
        __syncthreads();
    }

    int c0 = tx * 4;
    float bs[4], sc[4], sh[4];
    #pragma unroll
    for (int j = 0; j < 4; j++) {
        int c = c0 + j;
        float s = gamma[c] * rsqrtf(rvar[c] + 1e-5f);
        sc[j] = s;
        sh[j] = beta[c] - rmean[c] * s;
        bs[j] = bias[c];
    }
    #pragma unroll
    for (int i = 0; i < 8; i++) {
        int r = m0 + ty * 8 + i;
        if (r < n) {
            float a = (am != nullptr) ? am[r] : 1.0f;
            float4 o;
            o.x = fmaxf((acc[i][0] * a + bs[0]) * sc[0] + sh[0], 0.f);
            o.y = fmaxf((acc[i][1] * a + bs[1]) * sc[1] + sh[1], 0.f);
            o.z = fmaxf((acc[i][2] * a + bs[2]) * sc[2] + sh[2], 0.f);
            o.w = fmaxf((acc[i][3] * a + bs[3]) * sc[3] + sh[3], 0.f);
            *(float4*)(Y + (size_t)r * NF + c0) = o;
        }
    }
}

// ---------------------------------------------------------------------------
// t = h1 @ W2^T  (N x 40), warp-per-node with shfl reduction; W2 in smem.
// ---------------------------------------------------------------------------
__global__ __launch_bounds__(256) void tgemm_kernel(
    const float* __restrict__ X, const float* __restrict__ W2,
    float* __restrict__ T, int n)
{
    __shared__ float Wsm[NCLS * NF];
    for (int i = threadIdx.x; i < NCLS * NF / 4; i += 256)
        ((float4*)Wsm)[i] = ((const float4*)W2)[i];
    __syncthreads();

    int lane = threadIdx.x & 31;
    int warp = threadIdx.x >> 5;

    for (int node = blockIdx.x * 8 + warp; node < n; node += gridDim.x * 8) {
        float4 xv = *(const float4*)(X + (size_t)node * NF + lane * 4);
        float v0 = 0.f, v1 = 0.f;
        #pragma unroll
        for (int c = 0; c < NCLS; c++) {
            float4 wv = *(const float4*)&Wsm[c * NF + lane * 4];
            float p = xv.x * wv.x + xv.y * wv.y + xv.z * wv.z + xv.w * wv.w;
            p += __shfl_xor_sync(0xffffffffu, p, 16);
            p += __shfl_xor_sync(0xffffffffu, p, 8);
            p += __shfl_xor_sync(0xffffffffu, p, 4);
            p += __shfl_xor_sync(0xffffffffu, p, 2);
            p += __shfl_xor_sync(0xffffffffu, p, 1);
            if (c == lane) v0 = p;
            if (c == lane + 32) v1 = p;
        }
        T[(size_t)node * NCLS + lane] = v0;
        if (lane < 8) T[(size_t)node * NCLS + 32 + lane] = v1;
    }
}

// ---------------------------------------------------------------------------
// out = log_softmax(O + b2) over 40 classes; warp per node, lanes 0..19 x2.
// ---------------------------------------------------------------------------
__global__ __launch_bounds__(256) void lsm_kernel(
    const float* __restrict__ O, const float* __restrict__ b2,
    float* __restrict__ out, int n)
{
    int w = (blockIdx.x * 256 + (int)threadIdx.x) >> 5;
    if (w >= n) return;
    int lane = threadIdx.x & 31;
    bool act = lane < 20;
    float2 v = make_float2(0.f, 0.f);
    if (act) {
        v = *(const float2*)(O + (size_t)w * NCLS + lane * 2);
        v.x += b2[lane * 2];
        v.y += b2[lane * 2 + 1];
    }
    float m = act ? fmaxf(v.x, v.y) : -INFINITY;
    #pragma unroll
    for (int d = 16; d; d >>= 1) m = fmaxf(m, __shfl_xor_sync(0xffffffffu, m, d));
    float e = act ? (__expf(v.x - m) + __expf(v.y - m)) : 0.f;
    #pragma unroll
    for (int d = 16; d; d >>= 1) e += __shfl_xor_sync(0xffffffffu, e, d);
    float lse = logf(e) + m;
    if (act) {
        float2 o = make_float2(v.x - lse, v.y - lse);
        *(float2*)(out + (size_t)w * NCLS + lane * 2) = o;
    }
}

// ---------------------------------------------------------------------------
// launch
// ---------------------------------------------------------------------------
extern "C" void kernel_launch(void* const* d_in, const int* in_sizes, int n_in,
                              void* d_out, int out_size)
{
    const float* x     = (const float*)d_in[0];
    const float* M     = (const float*)d_in[1];
    const float* AM    = (const float*)d_in[2];
    const int*   srcZ  = (const int*)  d_in[3];
    const int*   dstZ  = (const int*)  d_in[4];
    const float* valsZ = (const float*)d_in[5];
    const int*   src   = (const int*)  d_in[6];
    const int*   dst   = (const int*)  d_in[7];
    const float* vals  = (const float*)d_in[8];
    const float* W0  = (const float*)d_in[9];
    const float* b0  = (const float*)d_in[10];
    const float* g0  = (const float*)d_in[11];
    const float* be0 = (const float*)d_in[12];
    const float* rm0 = (const float*)d_in[13];
    const float* rv0 = (const float*)d_in[14];
    const float* W1  = (const float*)d_in[15];
    const float* b1  = (const float*)d_in[16];
    const float* g1  = (const float*)d_in[17];
    const float* be1 = (const float*)d_in[18];
    const float* rm1 = (const float*)d_in[19];
    const float* rv1 = (const float*)d_in[20];
    const float* W2  = (const float*)d_in[21];
    const float* b2  = (const float*)d_in[22];
    float* out = (float*)d_out;

    int n = in_sizes[1];
    int E = in_sizes[3];

    float *bufA, *bufB, *t40, *o40;
    int *rpZ, *rpA, *cnt, *cur, *srcZp, *srcAp;
    float *valZp, *valAp;
    cudaGetSymbolAddress((void**)&bufA, g_bufA);
    cudaGetSymbolAddress((void**)&bufB, g_bufB);
    cudaGetSymbolAddress((void**)&t40, g_t40);
    cudaGetSymbolAddress((void**)&o40, g_o40);
    cudaGetSymbolAddress((void**)&rpZ, g_rpZ);
    cudaGetSymbolAddress((void**)&rpA, g_rpA);
    cudaGetSymbolAddress((void**)&cnt, g_cnt);
    cudaGetSymbolAddress((void**)&cur, g_cur);
    cudaGetSymbolAddress((void**)&srcZp, g_srcZp);
    cudaGetSymbolAddress((void**)&valZp, g_valZp);
    cudaGetSymbolAddress((void**)&srcAp, g_srcAp);
    cudaGetSymbolAddress((void**)&valAp, g_valAp);

    int egrid = (E + 255) / 256;
    int ngrid = (n + 255) / 256;
    int wgrid = (n * 32 + 255) / 256;              // warp per node
    int ggrid = (n + GBM - 1) / GBM;
    int w3grid = (((n + 2) / 3) * 32 + 255) / 256; // 3 nodes per warp

    // --- CSR build: adjZ (fold M into values) ---
    zero2_int_kernel<<<ngrid, 256>>>(cnt, cur, n);
    count_kernel<<<egrid, 256>>>(dstZ, cnt, E);
    scan_kernel<<<1, 1024>>>(cnt, rpZ, n);
    fill_kernel<<<egrid, 256>>>(srcZ, dstZ, valsZ, M, rpZ, cur, srcZp, valZp, E);

    // --- CSR build: adj ---
    zero2_int_kernel<<<ngrid, 256>>>(cnt, cur, n);
    count_kernel<<<egrid, 256>>>(dst, cnt, E);
    scan_kernel<<<1, 1024>>>(cnt, rpA, n);
    fill_kernel<<<egrid, 256>>>(src, dst, vals, nullptr, rpA, cur, srcAp, valAp, E);

    // --- layer 0: h = bn_relu((spmm(adjZ, M*x) * AM) @ W0^T + b0) ---
    spmm_gather128<<<wgrid, 256>>>(x, srcZp, valZp, rpZ, bufA, n);
    gemm_bn_relu_kernel<<<ggrid, 256>>>(bufA, W0, b0, g0, be0, rm0, rv0, AM, bufB, n);

    // --- layer 1: h = bn_relu(spmm(adj, h) @ W1^T + b1) ---
    spmm_gather128<<<wgrid, 256>>>(bufB, srcAp, valAp, rpA, bufA, n);
    gemm_bn_relu_kernel<<<ggrid, 256>>>(bufA, W1, b1, g1, be1, rm1, rv1, nullptr, bufB, n);

    // --- layer 2 (commuted): t = h @ W2^T; out = log_softmax(spmm(adj, t) + b2) ---
    tgemm_kernel<<<1480, 256>>>(bufB, W2, t40, n);
    spmm_gather40<<<w3grid, 256>>>(t40, srcAp, valAp, rpA, o40, n);
    lsm_kernel<<<(n * 32 + 255) / 256, 256>>>(o40, b2, out, n);
}

// round 4
// speedup vs baseline: 2.1936x; 1.6256x over previous
#include <cuda_runtime.h>
#include <math.h>

#define NNODE 100000
#define NF 128
#define NCLS 40
#define EMAX 1600000

// ---------------------------------------------------------------------------
// Static device scratch
// ---------------------------------------------------------------------------
__device__ float g_bufA[(size_t)NNODE * NF];
__device__ float g_bufB[(size_t)NNODE * NF];
__device__ float g_t40[(size_t)NNODE * NCLS];
__device__ float g_o40[(size_t)NNODE * NCLS];
__device__ int   g_rpZ[NNODE + 1];
__device__ int   g_rpA[NNODE + 1];
__device__ int   g_cntZ[NNODE];
__device__ int   g_curZ[NNODE];
__device__ int   g_cntA[NNODE];
__device__ int   g_curA[NNODE];
__device__ int   g_srcZp[EMAX];
__device__ float g_valZp[EMAX];
__device__ int   g_srcAp[EMAX];
__device__ float g_valAp[EMAX];

__device__ __forceinline__ unsigned f2tf32(float f) {
    unsigned u;
    asm("cvt.rna.tf32.f32 %0, %1;" : "=r"(u) : "f"(f));
    return u;
}

// ---------------------------------------------------------------------------
// CSR build (both graphs fused): zero -> count -> scan(x2 blocks) -> fill
// ---------------------------------------------------------------------------
__global__ void zero4_kernel(int* a, int* b, int* c, int* d, int n) {
    int i = blockIdx.x * blockDim.x + threadIdx.x;
    if (i < n) { a[i] = 0; b[i] = 0; c[i] = 0; d[i] = 0; }
}

__global__ void count_both_kernel(const int* __restrict__ dstZ, const int* __restrict__ dstA,
                                  int* __restrict__ cntZ, int* __restrict__ cntA, int E) {
    int e = blockIdx.x * blockDim.x + threadIdx.x;
    if (e < E) {
        atomicAdd(&cntZ[dstZ[e]], 1);
        atomicAdd(&cntA[dstA[e]], 1);
    }
}

__global__ __launch_bounds__(1024) void scan_pair_kernel(
    const int* __restrict__ cntZ, int* __restrict__ rpZ,
    const int* __restrict__ cntA, int* __restrict__ rpA, int n)
{
    const int* cnt = (blockIdx.x == 0) ? cntZ : cntA;
    int* rp        = (blockIdx.x == 0) ? rpZ  : rpA;
    __shared__ int sums[1024];
    int t = threadIdx.x;
    int chunk = (n + 1023) >> 10;
    int lo = t * chunk;
    int hi = min(lo + chunk, n);
    int s = 0;
    for (int i = lo; i < hi; i++) s += cnt[i];
    sums[t] = s;
    __syncthreads();
    for (int d = 1; d < 1024; d <<= 1) {
        int v = (t >= d) ? sums[t - d] : 0;
        __syncthreads();
        sums[t] += v;
        __syncthreads();
    }
    int off = t ? sums[t - 1] : 0;
    for (int i = lo; i < hi; i++) { rp[i] = off; off += cnt[i]; }
    if (t == 1023) rp[n] = sums[1023];
}

__global__ void fill_both_kernel(
    const int* __restrict__ srcZ, const int* __restrict__ dstZ, const float* __restrict__ valsZ,
    const int* __restrict__ srcA, const int* __restrict__ dstA, const float* __restrict__ valsA,
    const float* __restrict__ Mv,
    const int* __restrict__ rpZ, int* __restrict__ curZ,
    const int* __restrict__ rpA, int* __restrict__ curA,
    int* __restrict__ srcZp, float* __restrict__ valZp,
    int* __restrict__ srcAp, float* __restrict__ valAp, int E)
{
    int e = blockIdx.x * blockDim.x + threadIdx.x;
    if (e >= E) return;
    {
        int d = dstZ[e];
        int slot = rpZ[d] + atomicAdd(&curZ[d], 1);
        int s = srcZ[e];
        srcZp[slot] = s;
        valZp[slot] = valsZ[e] * Mv[s];
    }
    {
        int d = dstA[e];
        int slot = rpA[d] + atomicAdd(&curA[d], 1);
        srcAp[slot] = srcA[e];
        valAp[slot] = valsA[e];
    }
}

// ---------------------------------------------------------------------------
// Gather SpMM (128-wide): one warp per destination node.
// ---------------------------------------------------------------------------
__global__ __launch_bounds__(256) void spmm_gather128(
    const float* __restrict__ X, const int* __restrict__ srcp,
    const float* __restrict__ valp, const int* __restrict__ rp,
    float* __restrict__ Y, int n)
{
    int w = (blockIdx.x * 256 + (int)threadIdx.x) >> 5;
    if (w >= n) return;
    int lane = threadIdx.x & 31;
    int beg = rp[w], end = rp[w + 1];
    float4 acc = make_float4(0.f, 0.f, 0.f, 0.f);
    #pragma unroll 4
    for (int j = beg; j < end; j++) {
        int   s = srcp[j];
        float v = valp[j];
        float4 xv = *(const float4*)(X + (size_t)s * NF + lane * 4);
        acc.x += v * xv.x; acc.y += v * xv.y;
        acc.z += v * xv.z; acc.w += v * xv.w;
    }
    *(float4*)(Y + (size_t)w * NF + lane * 4) = acc;
}

// ---------------------------------------------------------------------------
// Gather SpMM (40-wide): 10 lanes per node, 3 nodes per warp.
// ---------------------------------------------------------------------------
__global__ __launch_bounds__(256) void spmm_gather40(
    const float* __restrict__ T, const int* __restrict__ srcp,
    const float* __restrict__ valp, const int* __restrict__ rp,
    float* __restrict__ O, int n)
{
    int gw = (blockIdx.x * 256 + (int)threadIdx.x) >> 5;
    int lane = threadIdx.x & 31;
    int grp = lane / 10;
    int l   = lane - grp * 10;
    if (grp >= 3) return;
    int node = gw * 3 + grp;
    if (node >= n) return;
    int beg = rp[node], end = rp[node + 1];
    float4 acc = make_float4(0.f, 0.f, 0.f, 0.f);
    #pragma unroll 4
    for (int j = beg; j < end; j++) {
        int   s = srcp[j];
        float v = valp[j];
        float4 tv = *(const float4*)(T + (size_t)s * NCLS + l * 4);
        acc.x += v * tv.x; acc.y += v * tv.y;
        acc.z += v * tv.z; acc.w += v * tv.w;
    }
    *(float4*)(O + (size_t)node * NCLS + l * 4) = acc;
}

// ---------------------------------------------------------------------------
// TF32 tensor-core GEMM + bias + BN + ReLU.
// Block: 256 thr = 8 warps (2 warp_m x 4 warp_n). Tile: 64 rows x 128 cols.
// smem pitch 36 floats => all fragment LDS are bank-conflict-free.
// ---------------------------------------------------------------------------
#define PK 36

__device__ __forceinline__ void mma_tf32(float* c, const unsigned* a, unsigned b0, unsigned b1) {
    asm volatile(
        "mma.sync.aligned.m16n8k8.row.col.f32.tf32.tf32.f32 "
        "{%0,%1,%2,%3}, {%4,%5,%6,%7}, {%8,%9}, {%0,%1,%2,%3};"
        : "+f"(c[0]), "+f"(c[1]), "+f"(c[2]), "+f"(c[3])
        : "r"(a[0]), "r"(a[1]), "r"(a[2]), "r"(a[3]), "r"(b0), "r"(b1));
}

__global__ __launch_bounds__(256) void gemm_bn_relu_mma(
    const float* __restrict__ X, const float* __restrict__ W,
    const float* __restrict__ bias, const float* __restrict__ gamma,
    const float* __restrict__ beta, const float* __restrict__ rmean,
    const float* __restrict__ rvar, const float* __restrict__ am,
    float* __restrict__ Y, int n)
{
    __shared__ float Xs[64][PK];
    __shared__ float Ws[128][PK];
    __shared__ float s_sc[128], s_sh[128], s_bs[128];

    int tid  = threadIdx.x;
    int lane = tid & 31;
    int wid  = tid >> 5;
    int warp_m = wid & 1;
    int warp_n = wid >> 1;
    int m0 = blockIdx.x * 64;

    if (tid < 128) {
        float s = gamma[tid] * rsqrtf(rvar[tid] + 1e-5f);
        s_sc[tid] = s;
        s_sh[tid] = beta[tid] - rmean[tid] * s;
        s_bs[tid] = bias[tid];
    }

    float acc[2][4][4];
    #pragma unroll
    for (int i = 0; i < 2; i++)
        #pragma unroll
        for (int j = 0; j < 4; j++)
            #pragma unroll
            for (int q = 0; q < 4; q++) acc[i][j][q] = 0.f;

    int g = lane >> 2, t = lane & 3;

    for (int k0 = 0; k0 < NF; k0 += 32) {
        // X tile 64x32 (converted to tf32 at store time)
        #pragma unroll
        for (int q = 0; q < 2; q++) {
            int idx = tid * 2 + q;
            int r   = idx >> 3;
            int kc  = (idx & 7) * 4;
            float4 v = make_float4(0.f, 0.f, 0.f, 0.f);
            int gr = m0 + r;
            if (gr < n) v = *(const float4*)(X + (size_t)gr * NF + k0 + kc);
            float* p = &Xs[r][kc];
            p[0] = __uint_as_float(f2tf32(v.x));
            p[1] = __uint_as_float(f2tf32(v.y));
            p[2] = __uint_as_float(f2tf32(v.z));
            p[3] = __uint_as_float(f2tf32(v.w));
        }
        // W tile 128x32
        #pragma unroll
        for (int q = 0; q < 4; q++) {
            int idx = tid * 4 + q;
            int o   = idx >> 3;
            int kc  = (idx & 7) * 4;
            float4 v = *(const float4*)(W + (size_t)o * NF + k0 + kc);
            float* p = &Ws[o][kc];
            p[0] = __uint_as_float(f2tf32(v.x));
            p[1] = __uint_as_float(f2tf32(v.y));
            p[2] = __uint_as_float(f2tf32(v.z));
            p[3] = __uint_as_float(f2tf32(v.w));
        }
        __syncthreads();

        #pragma unroll
        for (int ks = 0; ks < 32; ks += 8) {
            unsigned a[2][4];
            #pragma unroll
            for (int ma = 0; ma < 2; ma++) {
                int rb = warp_m * 32 + ma * 16;
                a[ma][0] = __float_as_uint(Xs[rb + g    ][ks + t    ]);
                a[ma][1] = __float_as_uint(Xs[rb + g + 8][ks + t    ]);
                a[ma][2] = __float_as_uint(Xs[rb + g    ][ks + t + 4]);
                a[ma][3] = __float_as_uint(Xs[rb + g + 8][ks + t + 4]);
            }
            #pragma unroll
            for (int na = 0; na < 4; na++) {
                int nb = warp_n * 32 + na * 8;
                unsigned b0 = __float_as_uint(Ws[nb + g][ks + t    ]);
                unsigned b1 = __float_as_uint(Ws[nb + g][ks + t + 4]);
                mma_tf32(acc[0][na], a[0], b0, b1);
                mma_tf32(acc[1][na], a[1], b0, b1);
            }
        }
        __syncthreads();
    }

    // epilogue: out = relu((acc*am + bias)*scale + shift)
    #pragma unroll
    for (int ma = 0; ma < 2; ma++) {
        int r0 = m0 + warp_m * 32 + ma * 16 + g;
        int r1 = r0 + 8;
        float a0 = 1.f, a1 = 1.f;
        if (am != nullptr) {
            if (r0 < n) a0 = am[r0];
            if (r1 < n) a1 = am[r1];
        }
        #pragma unroll
        for (int na = 0; na < 4; na++) {
            int c = warp_n * 32 + na * 8 + 2 * t;
            float sc0 = s_sc[c], sc1 = s_sc[c + 1];
            float sh0 = s_sh[c], sh1 = s_sh[c + 1];
            float bs0 = s_bs[c], bs1 = s_bs[c + 1];
            if (r0 < n) {
                float2 o;
                o.x = fmaxf((acc[ma][na][0] * a0 + bs0) * sc0 + sh0, 0.f);
                o.y = fmaxf((acc[ma][na][1] * a0 + bs1) * sc1 + sh1, 0.f);
                *(float2*)(Y + (size_t)r0 * NF + c) = o;
            }
            if (r1 < n) {
                float2 o;
                o.x = fmaxf((acc[ma][na][2] * a1 + bs0) * sc0 + sh0, 0.f);
                o.y = fmaxf((acc[ma][na][3] * a1 + bs1) * sc1 + sh1, 0.f);
                *(float2*)(Y + (size_t)r1 * NF + c) = o;
            }
        }
    }
}

// ---------------------------------------------------------------------------
// TF32 GEMM for t = h @ W2^T (N x 40). Block 256 thr = 8 warps, 128 rows.
// Each warp: 16 rows x 40 cols (5 n-atoms).
// ---------------------------------------------------------------------------
__global__ __launch_bounds__(256) void tgemm_mma(
    const float* __restrict__ X, const float* __restrict__ W2,
    float* __restrict__ T, int n)
{
    __shared__ float Xs[128][PK];
    __shared__ float Ws[NCLS][PK];

    int tid  = threadIdx.x;
    int lane = tid & 31;
    int wid  = tid >> 5;
    int m0 = blockIdx.x * 128;
    int g = lane >> 2, t = lane & 3;

    float acc[5][4];
    #pragma unroll
    for (int i = 0; i < 5; i++)
        #pragma unroll
        for (int q = 0; q < 4; q++) acc[i][q] = 0.f;

    for (int k0 = 0; k0 < NF; k0 += 32) {
        #pragma unroll
        for (int q = 0; q < 4; q++) {
            int idx = tid * 4 + q;          // 0..1023 -> 128 rows x 8 f4
            int r   = idx >> 3;
            int kc  = (idx & 7) * 4;
            float4 v = make_float4(0.f, 0.f, 0.f, 0.f);
            int gr = m0 + r;
            if (gr < n) v = *(const float4*)(X + (size_t)gr * NF + k0 + kc);
            float* p = &Xs[r][kc];
            p[0] = __uint_as_float(f2tf32(v.x));
            p[1] = __uint_as_float(f2tf32(v.y));
            p[2] = __uint_as_float(f2tf32(v.z));
            p[3] = __uint_as_float(f2tf32(v.w));
        }
        for (int idx = tid; idx < NCLS * 8; idx += 256) {
            int o  = idx >> 3;
            int kc = (idx & 7) * 4;
            float4 v = *(const float4*)(W2 + (size_t)o * NF + k0 + kc);
            float* p = &Ws[o][kc];
            p[0] = __uint_as_float(f2tf32(v.x));
            p[1] = __uint_as_float(f2tf32(v.y));
            p[2] = __uint_as_float(f2tf32(v.z));
            p[3] = __uint_as_float(f2tf32(v.w));
        }
        __syncthreads();

        #pragma unroll
        for (int ks = 0; ks < 32; ks += 8) {
            int rb = wid * 16;
            unsigned a[4];
            a[0] = __float_as_uint(Xs[rb + g    ][ks + t    ]);
            a[1] = __float_as_uint(Xs[rb + g + 8][ks + t    ]);
            a[2] = __float_as_uint(Xs[rb + g    ][ks + t + 4]);
            a[3] = __float_as_uint(Xs[rb + g + 8][ks + t + 4]);
            #pragma unroll
            for (int na = 0; na < 5; na++) {
                unsigned b0 = __float_as_uint(Ws[na * 8 + g][ks + t    ]);
                unsigned b1 = __float_as_uint(Ws[na * 8 + g][ks + t + 4]);
                mma_tf32(acc[na], a, b0, b1);
            }
        }
        __syncthreads();
    }

    int r0 = m0 + wid * 16 + g;
    int r1 = r0 + 8;
    #pragma unroll
    for (int na = 0; na < 5; na++) {
        int c = na * 8 + 2 * t;
        if (r0 < n) *(float2*)(T + (size_t)r0 * NCLS + c) = make_float2(acc[na][0], acc[na][1]);
        if (r1 < n) *(float2*)(T + (size_t)r1 * NCLS + c) = make_float2(acc[na][2], acc[na][3]);
    }
}

// ---------------------------------------------------------------------------
// out = log_softmax(O + b2) over 40 classes; warp per node.
// ---------------------------------------------------------------------------
__global__ __launch_bounds__(256) void lsm_kernel(
    const float* __restrict__ O, const float* __restrict__ b2,
    float* __restrict__ out, int n)
{
    int w = (blockIdx.x * 256 + (int)threadIdx.x) >> 5;
    if (w >= n) return;
    int lane = threadIdx.x & 31;
    bool act = lane < 20;
    float2 v = make_float2(0.f, 0.f);
    if (act) {
        v = *(const float2*)(O + (size_t)w * NCLS + lane * 2);
        v.x += b2[lane * 2];
        v.y += b2[lane * 2 + 1];
    }
    float m = act ? fmaxf(v.x, v.y) : -INFINITY;
    #pragma unroll
    for (int d = 16; d; d >>= 1) m = fmaxf(m, __shfl_xor_sync(0xffffffffu, m, d));
    float e = act ? (__expf(v.x - m) + __expf(v.y - m)) : 0.f;
    #pragma unroll
    for (int d = 16; d; d >>= 1) e += __shfl_xor_sync(0xffffffffu, e, d);
    float lse = logf(e) + m;
    if (act) {
        float2 o = make_float2(v.x - lse, v.y - lse);
        *(float2*)(out + (size_t)w * NCLS + lane * 2) = o;
    }
}

// ---------------------------------------------------------------------------
// launch
// ---------------------------------------------------------------------------
extern "C" void kernel_launch(void* const* d_in, const int* in_sizes, int n_in,
                              void* d_out, int out_size)
{
    const float* x     = (const float*)d_in[0];
    const float* M     = (const float*)d_in[1];
    const float* AM    = (const float*)d_in[2];
    const int*   srcZ  = (const int*)  d_in[3];
    const int*   dstZ  = (const int*)  d_in[4];
    const float* valsZ = (const float*)d_in[5];
    const int*   src   = (const int*)  d_in[6];
    const int*   dst   = (const int*)  d_in[7];
    const float* vals  = (const float*)d_in[8];
    const float* W0  = (const float*)d_in[9];
    const float* b0  = (const float*)d_in[10];
    const float* g0  = (const float*)d_in[11];
    const float* be0 = (const float*)d_in[12];
    const float* rm0 = (const float*)d_in[13];
    const float* rv0 = (const float*)d_in[14];
    const float* W1  = (const float*)d_in[15];
    const float* b1  = (const float*)d_in[16];
    const float* g1  = (const float*)d_in[17];
    const float* be1 = (const float*)d_in[18];
    const float* rm1 = (const float*)d_in[19];
    const float* rv1 = (const float*)d_in[20];
    const float* W2  = (const float*)d_in[21];
    const float* b2  = (const float*)d_in[22];
    float* out = (float*)d_out;

    int n = in_sizes[1];
    int E = in_sizes[3];

    float *bufA, *bufB, *t40, *o40, *valZp, *valAp;
    int *rpZ, *rpA, *cntZ, *curZ, *cntA, *curA, *srcZp, *srcAp;
    cudaGetSymbolAddress((void**)&bufA, g_bufA);
    cudaGetSymbolAddress((void**)&bufB, g_bufB);
    cudaGetSymbolAddress((void**)&t40, g_t40);
    cudaGetSymbolAddress((void**)&o40, g_o40);
    cudaGetSymbolAddress((void**)&rpZ, g_rpZ);
    cudaGetSymbolAddress((void**)&rpA, g_rpA);
    cudaGetSymbolAddress((void**)&cntZ, g_cntZ);
    cudaGetSymbolAddress((void**)&curZ, g_curZ);
    cudaGetSymbolAddress((void**)&cntA, g_cntA);
    cudaGetSymbolAddress((void**)&curA, g_curA);
    cudaGetSymbolAddress((void**)&srcZp, g_srcZp);
    cudaGetSymbolAddress((void**)&valZp, g_valZp);
    cudaGetSymbolAddress((void**)&srcAp, g_srcAp);
    cudaGetSymbolAddress((void**)&valAp, g_valAp);

    int egrid  = (E + 255) / 256;
    int ngrid  = (n + 255) / 256;
    int wgrid  = (n * 32 + 255) / 256;
    int ggrid  = (n + 63) / 64;
    int tggrid = (n + 127) / 128;
    int w3grid = (((n + 2) / 3) * 32 + 255) / 256;

    // --- fused CSR build for both graphs ---
    zero4_kernel<<<ngrid, 256>>>(cntZ, curZ, cntA, curA, n);
    count_both_kernel<<<egrid, 256>>>(dstZ, dst, cntZ, cntA, E);
    scan_pair_kernel<<<2, 1024>>>(cntZ, rpZ, cntA, rpA, n);
    fill_both_kernel<<<egrid, 256>>>(srcZ, dstZ, valsZ, src, dst, vals, M,
                                     rpZ, curZ, rpA, curA,
                                     srcZp, valZp, srcAp, valAp, E);

    // --- layer 0 ---
    spmm_gather128<<<wgrid, 256>>>(x, srcZp, valZp, rpZ, bufA, n);
    gemm_bn_relu_mma<<<ggrid, 256>>>(bufA, W0, b0, g0, be0, rm0, rv0, AM, bufB, n);

    // --- layer 1 ---
    spmm_gather128<<<wgrid, 256>>>(bufB, srcAp, valAp, rpA, bufA, n);
    gemm_bn_relu_mma<<<ggrid, 256>>>(bufA, W1, b1, g1, be1, rm1, rv1, nullptr, bufB, n);

    // --- layer 2 (commuted) ---
    tgemm_mma<<<tggrid, 256>>>(bufB, W2, t40, n);
    spmm_gather40<<<w3grid, 256>>>(t40, srcAp, valAp, rpA, o40, n);
    lsm_kernel<<<(n * 32 + 255) / 256, 256>>>(o40, b2, out, n);
}